// round 5
// baseline (speedup 1.0000x reference)
#include <cuda_runtime.h>
#include <cstdint>
#include <math.h>

// Problem constants
#define BB 4
#define SS 4096
#define NN 4096
#define CC 32

#define KCH 64               // k (n) per staged chunk
#define NSTAGE (NN / KCH)    // 64
#define STILES (SS / 64)     // 64 s-tiles of 64 rows
#define NTHREADS 256         // 8 warps: 4 row-groups x 2 K-halves
#define XPAD 40              // xs row stride in floats (conflict-free fragment loads)

typedef unsigned long long ull;

// ---- packed f32x2 helpers ----
__device__ __forceinline__ ull pk2(float lo, float hi) {
    ull r; asm("mov.b64 %0, {%1, %2};" : "=l"(r) : "f"(lo), "f"(hi)); return r;
}
__device__ __forceinline__ float2 upk2(ull v) {
    float lo, hi; asm("mov.b64 {%0, %1}, %2;" : "=f"(lo), "=f"(hi) : "l"(v));
    return make_float2(lo, hi);
}
__device__ __forceinline__ ull fma2n(ull a, ull b, ull c) {
    ull r; asm("fma.rn.f32x2 %0, %1, %2, %3;" : "=l"(r) : "l"(a), "l"(b), "l"(c)); return r;
}
__device__ __forceinline__ ull mul2(ull a, ull b) {
    ull r; asm("mul.rn.f32x2 %0, %1, %2;" : "=l"(r) : "l"(a), "l"(b)); return r;
}
__device__ __forceinline__ ull add2(ull a, ull b) {
    ull r; asm("add.rn.f32x2 %0, %1, %2;" : "=l"(r) : "l"(a), "l"(b)); return r;
}

// fp32 -> tf32 (round to nearest) as a raw b32 for mma operands
__device__ __forceinline__ uint32_t cvt_tf32(float v) {
    uint32_t r; asm("cvt.rna.tf32.f32 %0, %1;" : "=r"(r) : "f"(v)); return r;
}
__device__ __forceinline__ float cvt_tf32f(float v) {
    return __uint_as_float(cvt_tf32(v));
}

// m16n8k8 tf32 HMMA, D += A*B
__device__ __forceinline__ void mma8(float d[4], const uint32_t a[4],
                                     uint32_t b0, uint32_t b1) {
    asm volatile(
        "mma.sync.aligned.m16n8k8.row.col.f32.tf32.tf32.f32 "
        "{%0,%1,%2,%3}, {%4,%5,%6,%7}, {%8,%9}, {%0,%1,%2,%3};"
        : "+f"(d[0]), "+f"(d[1]), "+f"(d[2]), "+f"(d[3])
        : "r"(a[0]), "r"(a[1]), "r"(a[2]), "r"(a[3]), "r"(b0), "r"(b1));
}

// Range reduction: phase = k*2pi + r, |r| <= pi
#define INV2PI   0.15915493667125701904f
#define TWOPI_A  6.28318548202514648438f
#define TWOPI_B  (-1.74845552749343265e-7f)
#define MAGIC    12582912.0f    /* 1.5 * 2^23 */
#define ROWK     (-1.5339807878856412e-3f)   /* fl(-2*pi/4096) */

__global__ __launch_bounds__(NTHREADS, 2)
void fudft_hmma(const float* __restrict__ x,
                const float* __restrict__ t,
                const float* __restrict__ freqs,
                float* __restrict__ out) {
    // cols_sm doubles as the K-half exchange buffer in the epilogue
    __shared__ __align__(16) float cols_sm[NN];        // 16 KB
    __shared__ __align__(16) float xs[KCH * XPAD];     // 10.24 KB

    const int tid  = threadIdx.x;
    const int wid  = tid >> 5;
    const int lane = tid & 31;
    const int wg   = wid & 3;       // row group 0..3 (16 rows each)
    const int kh   = wid >> 2;      // K-half 0/1
    const int g    = lane >> 2;     // 0..7
    const int qid  = lane & 3;      // 0..3

    const int bx    = blockIdx.x;   // 0..255
    const int stile = bx & (STILES - 1);
    const int b     = bx >> 6;

    // ---- stage cols for the whole batch row (once) ----
    {
        const float4* t4 = (const float4*)(t + (size_t)b * NN);
        float4* c4 = (float4*)cols_sm;
#pragma unroll
        for (int r = 0; r < NN / 4 / NTHREADS; ++r) {
            float4 v = t4[tid + NTHREADS * r];
            v.x *= 4095.0f; v.y *= 4095.0f; v.z *= 4095.0f; v.w *= 4095.0f;
            c4[tid + NTHREADS * r] = v;
        }
    }

    // ---- per-thread row frequencies (A-fragment rows g and g+8) ----
    const int s_base = stile * 64 + wg * 16;
    const float rs0 = (freqs[s_base + g]     * 4095.0f) * ROWK;
    const float rs1 = (freqs[s_base + g + 8] * 4095.0f) * ROWK;
    const ull rs0_2 = pk2(rs0, rs0);
    const ull rs1_2 = pk2(rs1, rs1);
    const ull inv2pi2 = pk2(INV2PI, INV2PI);
    const ull magic2  = pk2(MAGIC, MAGIC);
    const ull nmagic2 = pk2(-MAGIC, -MAGIC);
    const ull nA2     = pk2(-TWOPI_A, -TWOPI_A);
    const ull nB2     = pk2(-TWOPI_B, -TWOPI_B);

    float dre[4][4], dim[4][4];
#pragma unroll
    for (int nt = 0; nt < 4; ++nt)
#pragma unroll
        for (int j = 0; j < 4; ++j) { dre[nt][j] = 0.0f; dim[nt][j] = 0.0f; }

    const float4* xg = (const float4*)(x + (size_t)b * NN * CC);
    const int kk = tid >> 3;             // staging row (k)
    const int cc = (tid & 7) * 4;        // staging col (c)

    // prefetch chunk 0
    float4 v0 = xg[tid];
    float4 v1 = xg[tid + NTHREADS];

#pragma unroll 1
    for (int st = 0; st < NSTAGE; ++st) {
        // store prefetched chunk (tf32-rounded)
        {
            float4 w0 = make_float4(cvt_tf32f(v0.x), cvt_tf32f(v0.y),
                                    cvt_tf32f(v0.z), cvt_tf32f(v0.w));
            float4 w1 = make_float4(cvt_tf32f(v1.x), cvt_tf32f(v1.y),
                                    cvt_tf32f(v1.z), cvt_tf32f(v1.w));
            *(float4*)(xs + kk * XPAD + cc)        = w0;
            *(float4*)(xs + (kk + 32) * XPAD + cc) = w1;
        }
        __syncthreads();

        // prefetch next chunk early
        if (st < NSTAGE - 1) {
            v0 = xg[(st + 1) * 512 + tid];
            v1 = xg[(st + 1) * 512 + tid + NTHREADS];
        }

        const float* cols_loc = cols_sm + st * KCH;
        const float* bp  = xs + qid * XPAD + g;      // b0 base (k = qid)
        const float* bp4 = bp + 4 * XPAD;            // b1 base (k = qid+4)

        // this warp covers ks = kh*4 .. kh*4+3
#pragma unroll
        for (int ks2 = 0; ks2 < 4; ++ks2) {
            const int k0 = (kh * 4 + ks2) * 8;
            const float colA = cols_loc[k0 + qid];
            const float colB = cols_loc[k0 + qid + 4];
            const ull tAB = pk2(colA, colB);
            ull ph0 = mul2(rs0_2, tAB);
            ull ph1 = mul2(rs1_2, tAB);
            ull m0 = fma2n(ph0, inv2pi2, magic2);
            ull m1 = fma2n(ph1, inv2pi2, magic2);
            ull k0v = add2(m0, nmagic2);
            ull k1v = add2(m1, nmagic2);
            ull r0v = fma2n(k0v, nA2, ph0); r0v = fma2n(k0v, nB2, r0v);
            ull r1v = fma2n(k1v, nA2, ph1); r1v = fma2n(k1v, nB2, r1v);
            const float2 ra = upk2(r0v);
            const float2 rb = upk2(r1v);

            uint32_t ac[4], as_[4];
            ac[0] = cvt_tf32(__cosf(ra.x)); as_[0] = cvt_tf32(__sinf(ra.x));
            ac[1] = cvt_tf32(__cosf(rb.x)); as_[1] = cvt_tf32(__sinf(rb.x));
            ac[2] = cvt_tf32(__cosf(ra.y)); as_[2] = cvt_tf32(__sinf(ra.y));
            ac[3] = cvt_tf32(__cosf(rb.y)); as_[3] = cvt_tf32(__sinf(rb.y));

            const float* b0p = bp  + k0 * XPAD;
            const float* b1p = bp4 + k0 * XPAD;
#pragma unroll
            for (int nt = 0; nt < 4; ++nt) {
                const uint32_t b0 = __float_as_uint(b0p[nt * 8]);
                const uint32_t b1 = __float_as_uint(b1p[nt * 8]);
                mma8(dre[nt], ac,  b0, b1);
                mma8(dim[nt], as_, b0, b1);
            }
        }
        __syncthreads();
    }

    // ---- merge K-halves through smem (reuse cols_sm), then write magnitudes ----
    // exchange layout: float4 slot per (wg, j, lane): addr = ((wg*8 + j)*32 + lane)*4 floats
    if (kh == 1) {
        float4* ex = (float4*)cols_sm;
#pragma unroll
        for (int nt = 0; nt < 4; ++nt) {
            ex[(wg * 8 + nt * 2)     * 32 + lane] = *(const float4*)dre[nt];
            ex[(wg * 8 + nt * 2 + 1) * 32 + lane] = *(const float4*)dim[nt];
        }
    }
    __syncthreads();
    if (kh == 0) {
        const float4* ex = (const float4*)cols_sm;
        const int s0 = s_base + g;
        const int s1 = s0 + 8;
        const bool z0 = (s0 == 0) || (s0 == SS - 1);
        const bool z1 = (s1 == 0) || (s1 == SS - 1);
        float* o0 = out + ((size_t)b * SS + s0) * CC;
        float* o1 = out + ((size_t)b * SS + s1) * CC;
#pragma unroll
        for (int nt = 0; nt < 4; ++nt) {
            float4 hre = ex[(wg * 8 + nt * 2)     * 32 + lane];
            float4 him = ex[(wg * 8 + nt * 2 + 1) * 32 + lane];
            float re0 = dre[nt][0] + hre.x, im0 = dim[nt][0] + him.x;
            float re1 = dre[nt][1] + hre.y, im1 = dim[nt][1] + him.y;
            float re2 = dre[nt][2] + hre.z, im2 = dim[nt][2] + him.z;
            float re3 = dre[nt][3] + hre.w, im3 = dim[nt][3] + him.w;
            const int c = nt * 8 + 2 * qid;
            float2 w;
            w.x = z0 ? 0.0f : sqrtf(fmaf(re0, re0, im0 * im0)) * 0.015625f;
            w.y = z0 ? 0.0f : sqrtf(fmaf(re1, re1, im1 * im1)) * 0.015625f;
            *(float2*)(o0 + c) = w;
            w.x = z1 ? 0.0f : sqrtf(fmaf(re2, re2, im2 * im2)) * 0.015625f;
            w.y = z1 ? 0.0f : sqrtf(fmaf(re3, re3, im3 * im3)) * 0.015625f;
            *(float2*)(o1 + c) = w;
        }
    }
}

extern "C" void kernel_launch(void* const* d_in, const int* in_sizes, int n_in,
                              void* d_out, int out_size) {
    const float* x     = (const float*)d_in[0];   // [4,4096,32]
    const float* t     = (const float*)d_in[1];   // [4,4096]
    const float* freqs = (const float*)d_in[2];   // [4096]
    float* out = (float*)d_out;                   // [4,4096,32]

    fudft_hmma<<<BB * STILES, NTHREADS>>>(x, t, freqs, out);
}

// round 6
// speedup vs baseline: 1.1866x; 1.1866x over previous
#include <cuda_runtime.h>
#include <cstdint>
#include <math.h>

// Problem constants
#define BB 4
#define SS 4096
#define NN 4096
#define CC 32

#define KCH 128              // k (n) per staged chunk
#define NSTAGE (NN / KCH)    // 32
#define STILES (SS / 128)    // 32 s-tiles of 128 rows
#define NTHREADS 512         // 16 warps: 8 row-groups x 2 K-halves
#define XPAD 40              // xs row stride in floats (conflict-free fragment loads)

typedef unsigned long long ull;

// ---- packed f32x2 helpers ----
__device__ __forceinline__ ull pk2(float lo, float hi) {
    ull r; asm("mov.b64 %0, {%1, %2};" : "=l"(r) : "f"(lo), "f"(hi)); return r;
}
__device__ __forceinline__ float2 upk2(ull v) {
    float lo, hi; asm("mov.b64 {%0, %1}, %2;" : "=f"(lo), "=f"(hi) : "l"(v));
    return make_float2(lo, hi);
}
__device__ __forceinline__ ull fma2n(ull a, ull b, ull c) {
    ull r; asm("fma.rn.f32x2 %0, %1, %2, %3;" : "=l"(r) : "l"(a), "l"(b), "l"(c)); return r;
}
__device__ __forceinline__ ull mul2(ull a, ull b) {
    ull r; asm("mul.rn.f32x2 %0, %1, %2;" : "=l"(r) : "l"(a), "l"(b)); return r;
}
__device__ __forceinline__ ull add2(ull a, ull b) {
    ull r; asm("add.rn.f32x2 %0, %1, %2;" : "=l"(r) : "l"(a), "l"(b)); return r;
}

// fp32 -> tf32 RNE, used for B staging only (A relies on HW tf32 truncation)
__device__ __forceinline__ float cvt_tf32f(float v) {
    uint32_t r; asm("cvt.rna.tf32.f32 %0, %1;" : "=r"(r) : "f"(v));
    return __uint_as_float(r);
}

// m16n8k8 tf32 HMMA, D += A*B
__device__ __forceinline__ void mma8(float d[4], const uint32_t a[4],
                                     uint32_t b0, uint32_t b1) {
    asm volatile(
        "mma.sync.aligned.m16n8k8.row.col.f32.tf32.tf32.f32 "
        "{%0,%1,%2,%3}, {%4,%5,%6,%7}, {%8,%9}, {%0,%1,%2,%3};"
        : "+f"(d[0]), "+f"(d[1]), "+f"(d[2]), "+f"(d[3])
        : "r"(a[0]), "r"(a[1]), "r"(a[2]), "r"(a[3]), "r"(b0), "r"(b1));
}

// Range reduction: phase = k*2pi + r, |r| <= pi
#define INV2PI   0.15915493667125701904f
#define TWOPI_A  6.28318548202514648438f
#define TWOPI_B  (-1.74845552749343265e-7f)
#define MAGIC    12582912.0f    /* 1.5 * 2^23 */
#define ROWK     (-1.5339807878856412e-3f)   /* fl(-2*pi/4096) */

__global__ __launch_bounds__(NTHREADS, 1)
void fudft_hmma(const float* __restrict__ x,
                const float* __restrict__ t,
                const float* __restrict__ freqs,
                float* __restrict__ out) {
    // cols_sm doubles as the K-half exchange buffer in the epilogue (16 KB)
    __shared__ __align__(16) float cols_sm[NN];
    __shared__ __align__(16) float xs[KCH * XPAD];     // 20.48 KB

    const int tid  = threadIdx.x;
    const int wid  = tid >> 5;
    const int lane = tid & 31;
    const int wg   = wid & 7;       // row group 0..7 (16 rows each)
    const int kh   = wid >> 3;      // K-half 0/1
    const int g    = lane >> 2;     // 0..7
    const int qid  = lane & 3;      // 0..3

    const int bx    = blockIdx.x;   // 0..127
    const int stile = bx & (STILES - 1);
    const int b     = bx >> 5;

    // ---- stage cols for the whole batch row (once) ----
    {
        const float4* t4 = (const float4*)(t + (size_t)b * NN);
        float4* c4 = (float4*)cols_sm;
#pragma unroll
        for (int r = 0; r < NN / 4 / NTHREADS; ++r) {
            float4 v = t4[tid + NTHREADS * r];
            v.x *= 4095.0f; v.y *= 4095.0f; v.z *= 4095.0f; v.w *= 4095.0f;
            c4[tid + NTHREADS * r] = v;
        }
    }

    // ---- per-thread row frequencies (A-fragment rows g and g+8) ----
    const int s_base = stile * 128 + wg * 16;
    const float rs0 = (freqs[s_base + g]     * 4095.0f) * ROWK;
    const float rs1 = (freqs[s_base + g + 8] * 4095.0f) * ROWK;
    const ull rs0_2 = pk2(rs0, rs0);
    const ull rs1_2 = pk2(rs1, rs1);
    const ull inv2pi2 = pk2(INV2PI, INV2PI);
    const ull magic2  = pk2(MAGIC, MAGIC);
    const ull nmagic2 = pk2(-MAGIC, -MAGIC);
    const ull nA2     = pk2(-TWOPI_A, -TWOPI_A);
    const ull nB2     = pk2(-TWOPI_B, -TWOPI_B);

    float dre[4][4], dim[4][4];
#pragma unroll
    for (int nt = 0; nt < 4; ++nt)
#pragma unroll
        for (int j = 0; j < 4; ++j) { dre[nt][j] = 0.0f; dim[nt][j] = 0.0f; }

    const float4* xg = (const float4*)(x + (size_t)b * NN * CC);
    const int kk = tid >> 3;             // staging row (k) for fidx0: 0..63
    const int cc = (tid & 7) * 4;        // staging col (c)

    // B-fragment bases (loop-invariant)
    const float* bp  = xs + qid * XPAD + g;      // b0 base (k = qid)
    const float* bp4 = bp + 4 * XPAD;            // b1 base (k = qid+4)

    // prefetch chunk 0 (KCH*CC/4 = 1024 float4 per chunk; 2 per thread)
    float4 v0 = xg[tid];
    float4 v1 = xg[tid + NTHREADS];

#pragma unroll 1
    for (int st = 0; st < NSTAGE; ++st) {
        // store prefetched chunk (tf32 RNE)
        {
            float4 w0 = make_float4(cvt_tf32f(v0.x), cvt_tf32f(v0.y),
                                    cvt_tf32f(v0.z), cvt_tf32f(v0.w));
            float4 w1 = make_float4(cvt_tf32f(v1.x), cvt_tf32f(v1.y),
                                    cvt_tf32f(v1.z), cvt_tf32f(v1.w));
            *(float4*)(xs + kk * XPAD + cc)        = w0;
            *(float4*)(xs + (kk + 64) * XPAD + cc) = w1;
        }
        __syncthreads();

        // prefetch next chunk early
        if (st < NSTAGE - 1) {
            v0 = xg[(st + 1) * 1024 + tid];
            v1 = xg[(st + 1) * 1024 + tid + NTHREADS];
        }

        const float* cols_loc = cols_sm + st * KCH;

        // this warp covers ks = kh*8 .. kh*8+7 within the 128-k chunk
#pragma unroll
        for (int ks2 = 0; ks2 < 8; ++ks2) {
            const int k0 = kh * 64 + ks2 * 8;
            const float colA = cols_loc[k0 + qid];
            const float colB = cols_loc[k0 + qid + 4];
            const ull tAB = pk2(colA, colB);
            ull ph0 = mul2(rs0_2, tAB);
            ull ph1 = mul2(rs1_2, tAB);
            ull m0 = fma2n(ph0, inv2pi2, magic2);
            ull m1 = fma2n(ph1, inv2pi2, magic2);
            ull k0v = add2(m0, nmagic2);
            ull k1v = add2(m1, nmagic2);
            ull r0v = fma2n(k0v, nA2, ph0); r0v = fma2n(k0v, nB2, r0v);
            ull r1v = fma2n(k1v, nA2, ph1); r1v = fma2n(k1v, nB2, r1v);
            const float2 ra = upk2(r0v);
            const float2 rb = upk2(r1v);

            // raw f32 -> HMMA truncates to tf32 in HW (saves 8 CVTs)
            uint32_t ac[4], as_[4];
            ac[0] = __float_as_uint(__cosf(ra.x)); as_[0] = __float_as_uint(__sinf(ra.x));
            ac[1] = __float_as_uint(__cosf(rb.x)); as_[1] = __float_as_uint(__sinf(rb.x));
            ac[2] = __float_as_uint(__cosf(ra.y)); as_[2] = __float_as_uint(__sinf(ra.y));
            ac[3] = __float_as_uint(__cosf(rb.y)); as_[3] = __float_as_uint(__sinf(rb.y));

            const float* b0p = bp  + k0 * XPAD;
            const float* b1p = bp4 + k0 * XPAD;
#pragma unroll
            for (int nt = 0; nt < 4; ++nt) {
                const uint32_t b0 = __float_as_uint(b0p[nt * 8]);
                const uint32_t b1 = __float_as_uint(b1p[nt * 8]);
                mma8(dre[nt], ac,  b0, b1);
                mma8(dim[nt], as_, b0, b1);
            }
        }
        __syncthreads();
    }

    // ---- merge K-halves through cols_sm in 2 phases (nt pair per phase) ----
    const int s0 = s_base + g;
    const int s1 = s0 + 8;
    const bool z0 = (s0 == 0) || (s0 == SS - 1);
    const bool z1 = (s1 == 0) || (s1 == SS - 1);
    float* o0 = out + ((size_t)b * SS + s0) * CC;
    float* o1 = out + ((size_t)b * SS + s1) * CC;

#pragma unroll
    for (int p = 0; p < 2; ++p) {
        if (kh == 1) {
            float4* ex = (float4*)cols_sm;
#pragma unroll
            for (int j = 0; j < 2; ++j) {
                const int nt = 2 * p + j;
                ex[(wg * 4 + j * 2)     * 32 + lane] = *(const float4*)dre[nt];
                ex[(wg * 4 + j * 2 + 1) * 32 + lane] = *(const float4*)dim[nt];
            }
        }
        __syncthreads();
        if (kh == 0) {
            const float4* ex = (const float4*)cols_sm;
#pragma unroll
            for (int j = 0; j < 2; ++j) {
                const int nt = 2 * p + j;
                float4 hre = ex[(wg * 4 + j * 2)     * 32 + lane];
                float4 him = ex[(wg * 4 + j * 2 + 1) * 32 + lane];
                float re0 = dre[nt][0] + hre.x, im0 = dim[nt][0] + him.x;
                float re1 = dre[nt][1] + hre.y, im1 = dim[nt][1] + him.y;
                float re2 = dre[nt][2] + hre.z, im2 = dim[nt][2] + him.z;
                float re3 = dre[nt][3] + hre.w, im3 = dim[nt][3] + him.w;
                const int c = nt * 8 + 2 * qid;
                float2 w;
                w.x = z0 ? 0.0f : sqrtf(fmaf(re0, re0, im0 * im0)) * 0.015625f;
                w.y = z0 ? 0.0f : sqrtf(fmaf(re1, re1, im1 * im1)) * 0.015625f;
                *(float2*)(o0 + c) = w;
                w.x = z1 ? 0.0f : sqrtf(fmaf(re2, re2, im2 * im2)) * 0.015625f;
                w.y = z1 ? 0.0f : sqrtf(fmaf(re3, re3, im3 * im3)) * 0.015625f;
                *(float2*)(o1 + c) = w;
            }
        }
        if (p == 0) __syncthreads();
    }
}

extern "C" void kernel_launch(void* const* d_in, const int* in_sizes, int n_in,
                              void* d_out, int out_size) {
    const float* x     = (const float*)d_in[0];   // [4,4096,32]
    const float* t     = (const float*)d_in[1];   // [4,4096]
    const float* freqs = (const float*)d_in[2];   // [4096]
    float* out = (float*)d_out;                   // [4,4096,32]

    fudft_hmma<<<BB * STILES, NTHREADS>>>(x, t, freqs, out);
}

// round 7
// speedup vs baseline: 1.3653x; 1.1506x over previous
#include <cuda_runtime.h>
#include <cstdint>
#include <math.h>

// Problem constants
#define BB 4
#define SS 4096
#define NN 4096
#define CC 32

#define KCH 128              // k (n) per staged chunk
#define NSTAGE (NN / KCH)    // 32
#define STILES (SS / 128)    // 32 s-tiles of 128 rows
#define NTHREADS 512         // 16 warps: 8 row-groups x 2 K-halves
#define KP2 68               // xsh row stride in u32 (68 = 64 data + 4 pad, ==4 mod 32)

typedef unsigned long long ull;

// ---- packed f32x2 helpers ----
__device__ __forceinline__ ull pk2(float lo, float hi) {
    ull r; asm("mov.b64 %0, {%1, %2};" : "=l"(r) : "f"(lo), "f"(hi)); return r;
}
__device__ __forceinline__ float2 upk2(ull v) {
    float lo, hi; asm("mov.b64 {%0, %1}, %2;" : "=f"(lo), "=f"(hi) : "l"(v));
    return make_float2(lo, hi);
}
__device__ __forceinline__ ull fma2n(ull a, ull b, ull c) {
    ull r; asm("fma.rn.f32x2 %0, %1, %2, %3;" : "=l"(r) : "l"(a), "l"(b), "l"(c)); return r;
}
__device__ __forceinline__ ull mul2(ull a, ull b) {
    ull r; asm("mul.rn.f32x2 %0, %1, %2;" : "=l"(r) : "l"(a), "l"(b)); return r;
}
__device__ __forceinline__ ull add2(ull a, ull b) {
    ull r; asm("add.rn.f32x2 %0, %1, %2;" : "=l"(r) : "l"(a), "l"(b)); return r;
}
// pack two f32 -> f16x2 (RNE). lo = low half of result.
__device__ __forceinline__ uint32_t f2h2(float lo, float hi) {
    uint32_t r; asm("cvt.rn.f16x2.f32 %0, %1, %2;" : "=r"(r) : "f"(hi), "f"(lo)); return r;
}

// m16n8k16 fp16 HMMA, D(f32) += A(f16)*B(f16)
__device__ __forceinline__ void mma16(float d[4], const uint32_t a[4],
                                      uint32_t b0, uint32_t b1) {
    asm volatile(
        "mma.sync.aligned.m16n8k16.row.col.f32.f16.f16.f32 "
        "{%0,%1,%2,%3}, {%4,%5,%6,%7}, {%8,%9}, {%0,%1,%2,%3};"
        : "+f"(d[0]), "+f"(d[1]), "+f"(d[2]), "+f"(d[3])
        : "r"(a[0]), "r"(a[1]), "r"(a[2]), "r"(a[3]), "r"(b0), "r"(b1));
}

// Range reduction: phase = k*2pi + r, |r| <= pi
#define INV2PI   0.15915493667125701904f
#define TWOPI_A  6.28318548202514648438f
#define TWOPI_B  (-1.74845552749343265e-7f)
#define MAGIC    12582912.0f    /* 1.5 * 2^23 */
#define ROWK     (-1.5339807878856412e-3f)   /* fl(-2*pi/4096) */

__global__ __launch_bounds__(NTHREADS, 1)
void fudft_hmma(const float* __restrict__ x,
                const float* __restrict__ t,
                const float* __restrict__ freqs,
                float* __restrict__ out) {
    // cols_sm doubles as the K-half exchange buffer in the epilogue (16 KB)
    __shared__ __align__(16) float cols_sm[NN];
    // X^T chunk as fp16 k-pairs: [c][kpair], row stride KP2 u32, XOR-swizzled
    __shared__ __align__(16) uint32_t xsh[CC * KP2];   // 8.7 KB

    const int tid  = threadIdx.x;
    const int wid  = tid >> 5;
    const int lane = tid & 31;
    const int wg   = wid & 7;       // row group 0..7 (16 rows each)
    const int kh   = wid >> 3;      // K-half 0/1
    const int g    = lane >> 2;     // 0..7
    const int qid  = lane & 3;      // 0..3

    const int bx    = blockIdx.x;   // 0..127
    const int stile = bx & (STILES - 1);
    const int b     = bx >> 5;

    // ---- stage cols for the whole batch row (once) ----
    {
        const float4* t4 = (const float4*)(t + (size_t)b * NN);
        float4* c4 = (float4*)cols_sm;
#pragma unroll
        for (int r = 0; r < NN / 4 / NTHREADS; ++r) {
            float4 v = t4[tid + NTHREADS * r];
            v.x *= 4095.0f; v.y *= 4095.0f; v.z *= 4095.0f; v.w *= 4095.0f;
            c4[tid + NTHREADS * r] = v;
        }
    }

    // ---- per-thread row frequencies (A-fragment rows g and g+8) ----
    const int s_base = stile * 128 + wg * 16;
    const float rs0 = (freqs[s_base + g]     * 4095.0f) * ROWK;
    const float rs1 = (freqs[s_base + g + 8] * 4095.0f) * ROWK;
    const ull rs0_2 = pk2(rs0, rs0);
    const ull rs1_2 = pk2(rs1, rs1);
    const ull inv2pi2 = pk2(INV2PI, INV2PI);
    const ull magic2  = pk2(MAGIC, MAGIC);
    const ull nmagic2 = pk2(-MAGIC, -MAGIC);
    const ull nA2     = pk2(-TWOPI_A, -TWOPI_A);
    const ull nB2     = pk2(-TWOPI_B, -TWOPI_B);

    float dre[4][4], dim[4][4];
#pragma unroll
    for (int nt = 0; nt < 4; ++nt)
#pragma unroll
        for (int j = 0; j < 4; ++j) { dre[nt][j] = 0.0f; dim[nt][j] = 0.0f; }

    // B-fragment u32 base offsets (swizzled), per n-tile; add K (=k0/2) per step
    uint32_t bb0[4], bb1[4];
#pragma unroll
    for (int nt = 0; nt < 4; ++nt) {
        const int xw = (2 * nt + (g >> 2)) & 7;
        bb0[nt] = (uint32_t)((8 * nt + g) * KP2 + (qid ^ xw));
        bb1[nt] = (uint32_t)((8 * nt + g) * KP2 + ((qid + 4) ^ xw));
    }

    // staging decomposition: this thread holds x[k][c0..c0+3], k = tid>>3
    const float4* xg = (const float4*)(x + (size_t)b * NN * CC);
    const int kk   = tid >> 3;        // 0..63
    const int aa   = tid & 7;         // c block: c0 = 4*aa; swz term = (c>>2)&7 = aa
    const int kodd = kk & 1;
    const int kcol = (kk >> 1) ^ aa;  // swizzled k-pair col for v0 (v1: +32)
    const int c0   = aa * 4;

    // prefetch chunk 0 (1024 float4 per chunk; 2 per thread)
    float4 v0 = xg[tid];
    float4 v1 = xg[tid + NTHREADS];

#pragma unroll 1
    for (int st = 0; st < NSTAGE; ++st) {
        // ---- stage chunk: fp32 -> fp16, k-paired via shfl/prmt, swizzled ----
        {
#pragma unroll
            for (int h = 0; h < 2; ++h) {
                const float4 v = h ? v1 : v0;
                const int col = kcol + 32 * h;      // bit5 untouched by swz
                uint32_t q0 = f2h2(v.x, v.y);       // halves (c0, c0+1), my k
                uint32_t q1 = f2h2(v.z, v.w);       // halves (c0+2, c0+3)
                uint32_t s0 = __shfl_xor_sync(0xffffffffu, q0, 8);
                uint32_t s1 = __shfl_xor_sync(0xffffffffu, q1, 8);
                if (!kodd) {
                    // rows c0, c0+1: (even-k = mine, odd-k = partner)
                    xsh[c0 * KP2 + col]       = __byte_perm(q0, s0, 0x5410);
                    xsh[(c0 + 1) * KP2 + col] = __byte_perm(q0, s0, 0x7632);
                } else {
                    // rows c0+2, c0+3: (even-k = partner, odd-k = mine)
                    xsh[(c0 + 2) * KP2 + col] = __byte_perm(s1, q1, 0x5410);
                    xsh[(c0 + 3) * KP2 + col] = __byte_perm(s1, q1, 0x7632);
                }
            }
        }
        __syncthreads();

        // prefetch next chunk early
        if (st < NSTAGE - 1) {
            v0 = xg[(st + 1) * 1024 + tid];
            v1 = xg[(st + 1) * 1024 + tid + NTHREADS];
        }

        const float* cols_loc = cols_sm + st * KCH;

        // this warp covers k16-steps kh*64 .. kh*64+63 within the 128-k chunk
#pragma unroll
        for (int ks2 = 0; ks2 < 4; ++ks2) {
            const int k0 = kh * 64 + ks2 * 16;
            // col pairs: (2qid, 2qid+1) and (8+2qid, 9+2qid)
            const ull cA = *(const ull*)(cols_loc + k0 + 2 * qid);
            const ull cB = *(const ull*)(cols_loc + k0 + 2 * qid + 8);

            ull p00 = mul2(rs0_2, cA), p01 = mul2(rs0_2, cB);
            ull p10 = mul2(rs1_2, cA), p11 = mul2(rs1_2, cB);
            ull m00 = fma2n(p00, inv2pi2, magic2), m01 = fma2n(p01, inv2pi2, magic2);
            ull m10 = fma2n(p10, inv2pi2, magic2), m11 = fma2n(p11, inv2pi2, magic2);
            ull k00 = add2(m00, nmagic2), k01 = add2(m01, nmagic2);
            ull k10 = add2(m10, nmagic2), k11 = add2(m11, nmagic2);
            ull r00 = fma2n(k00, nA2, p00); r00 = fma2n(k00, nB2, r00);
            ull r01 = fma2n(k01, nA2, p01); r01 = fma2n(k01, nB2, r01);
            ull r10 = fma2n(k10, nA2, p10); r10 = fma2n(k10, nB2, r10);
            ull r11 = fma2n(k11, nA2, p11); r11 = fma2n(k11, nB2, r11);
            const float2 f00 = upk2(r00), f01 = upk2(r01);
            const float2 f10 = upk2(r10), f11 = upk2(r11);

            // A fragments: a0=(g,k01) a1=(g+8,k01) a2=(g,k89) a3=(g+8,k89)
            uint32_t ac[4], as_[4];
            ac[0]  = f2h2(__cosf(f00.x), __cosf(f00.y));
            as_[0] = f2h2(__sinf(f00.x), __sinf(f00.y));
            ac[1]  = f2h2(__cosf(f10.x), __cosf(f10.y));
            as_[1] = f2h2(__sinf(f10.x), __sinf(f10.y));
            ac[2]  = f2h2(__cosf(f01.x), __cosf(f01.y));
            as_[2] = f2h2(__sinf(f01.x), __sinf(f01.y));
            ac[3]  = f2h2(__cosf(f11.x), __cosf(f11.y));
            as_[3] = f2h2(__sinf(f11.x), __sinf(f11.y));

            const uint32_t K = (uint32_t)(k0 >> 1);   // k-pair base (mult of 8)
#pragma unroll
            for (int nt = 0; nt < 4; ++nt) {
                const uint32_t b0 = xsh[bb0[nt] + K];
                const uint32_t b1 = xsh[bb1[nt] + K];
                mma16(dre[nt], ac,  b0, b1);
                mma16(dim[nt], as_, b0, b1);
            }
        }
        __syncthreads();
    }

    // ---- merge K-halves through cols_sm in 2 phases (nt pair per phase) ----
    const int s0g = s_base + g;
    const int s1g = s0g + 8;
    const bool z0 = (s0g == 0) || (s0g == SS - 1);
    const bool z1 = (s1g == 0) || (s1g == SS - 1);
    float* o0 = out + ((size_t)b * SS + s0g) * CC;
    float* o1 = out + ((size_t)b * SS + s1g) * CC;

#pragma unroll
    for (int p = 0; p < 2; ++p) {
        if (kh == 1) {
            float4* ex = (float4*)cols_sm;
#pragma unroll
            for (int j = 0; j < 2; ++j) {
                const int nt = 2 * p + j;
                ex[(wg * 4 + j * 2)     * 32 + lane] = *(const float4*)dre[nt];
                ex[(wg * 4 + j * 2 + 1) * 32 + lane] = *(const float4*)dim[nt];
            }
        }
        __syncthreads();
        if (kh == 0) {
            const float4* ex = (const float4*)cols_sm;
#pragma unroll
            for (int j = 0; j < 2; ++j) {
                const int nt = 2 * p + j;
                float4 hre = ex[(wg * 4 + j * 2)     * 32 + lane];
                float4 him = ex[(wg * 4 + j * 2 + 1) * 32 + lane];
                float re0 = dre[nt][0] + hre.x, im0 = dim[nt][0] + him.x;
                float re1 = dre[nt][1] + hre.y, im1 = dim[nt][1] + him.y;
                float re2 = dre[nt][2] + hre.z, im2 = dim[nt][2] + him.z;
                float re3 = dre[nt][3] + hre.w, im3 = dim[nt][3] + him.w;
                const int c = nt * 8 + 2 * qid;
                float2 w;
                w.x = z0 ? 0.0f : sqrtf(fmaf(re0, re0, im0 * im0)) * 0.015625f;
                w.y = z0 ? 0.0f : sqrtf(fmaf(re1, re1, im1 * im1)) * 0.015625f;
                *(float2*)(o0 + c) = w;
                w.x = z1 ? 0.0f : sqrtf(fmaf(re2, re2, im2 * im2)) * 0.015625f;
                w.y = z1 ? 0.0f : sqrtf(fmaf(re3, re3, im3 * im3)) * 0.015625f;
                *(float2*)(o1 + c) = w;
            }
        }
        if (p == 0) __syncthreads();
    }
}

extern "C" void kernel_launch(void* const* d_in, const int* in_sizes, int n_in,
                              void* d_out, int out_size) {
    const float* x     = (const float*)d_in[0];   // [4,4096,32]
    const float* t     = (const float*)d_in[1];   // [4,4096]
    const float* freqs = (const float*)d_in[2];   // [4096]
    float* out = (float*)d_out;                   // [4,4096,32]

    fudft_hmma<<<BB * STILES, NTHREADS>>>(x, t, freqs, out);
}

// round 8
// speedup vs baseline: 1.4224x; 1.0418x over previous
#include <cuda_runtime.h>
#include <cstdint>
#include <math.h>

// Problem constants
#define BB 4
#define SS 4096
#define NN 4096
#define CC 32

#define KCH 128              // k (n) per staged chunk
#define NSTAGE (NN / KCH)    // 32
#define STILES (SS / 128)    // 32 s-tiles of 128 rows
#define NTHREADS 512         // 16 warps: 8 row-groups x 2 K-halves
#define XST 68               // xsh row stride in u32 (64 k-pairs + 4 pad; 68/4 odd)
#define XBUF (CC * XST)      // u32 per buffer (2176)

typedef unsigned long long ull;

// ---- packed f32x2 helpers ----
__device__ __forceinline__ ull pk2(float lo, float hi) {
    ull r; asm("mov.b64 %0, {%1, %2};" : "=l"(r) : "f"(lo), "f"(hi)); return r;
}
__device__ __forceinline__ float2 upk2(ull v) {
    float lo, hi; asm("mov.b64 {%0, %1}, %2;" : "=f"(lo), "=f"(hi) : "l"(v));
    return make_float2(lo, hi);
}
__device__ __forceinline__ ull fma2n(ull a, ull b, ull c) {
    ull r; asm("fma.rn.f32x2 %0, %1, %2, %3;" : "=l"(r) : "l"(a), "l"(b), "l"(c)); return r;
}
__device__ __forceinline__ ull mul2(ull a, ull b) {
    ull r; asm("mul.rn.f32x2 %0, %1, %2;" : "=l"(r) : "l"(a), "l"(b)); return r;
}
__device__ __forceinline__ ull add2(ull a, ull b) {
    ull r; asm("add.rn.f32x2 %0, %1, %2;" : "=l"(r) : "l"(a), "l"(b)); return r;
}
// pack two f32 -> f16x2 (RNE). lo = low half of result.
__device__ __forceinline__ uint32_t f2h2(float lo, float hi) {
    uint32_t r; asm("cvt.rn.f16x2.f32 %0, %1, %2;" : "=r"(r) : "f"(hi), "f"(lo)); return r;
}

// m16n8k16 fp16 HMMA, D(f32) += A(f16)*B(f16)
__device__ __forceinline__ void mma16(float d[4], const uint32_t a[4],
                                      uint32_t b0, uint32_t b1) {
    asm volatile(
        "mma.sync.aligned.m16n8k16.row.col.f32.f16.f16.f32 "
        "{%0,%1,%2,%3}, {%4,%5,%6,%7}, {%8,%9}, {%0,%1,%2,%3};"
        : "+f"(d[0]), "+f"(d[1]), "+f"(d[2]), "+f"(d[3])
        : "r"(a[0]), "r"(a[1]), "r"(a[2]), "r"(a[3]), "r"(b0), "r"(b1));
}

// ldmatrix x4: four 8x8 b16 matrices; thread t supplies row address
__device__ __forceinline__ void ldsm4(uint32_t& r0, uint32_t& r1,
                                      uint32_t& r2, uint32_t& r3, uint32_t addr) {
    asm volatile("ldmatrix.sync.aligned.m8n8.x4.shared.b16 {%0,%1,%2,%3}, [%4];"
        : "=r"(r0), "=r"(r1), "=r"(r2), "=r"(r3) : "r"(addr));
}

// Range reduction: phase = k*2pi + r, |r| <= pi
#define INV2PI   0.15915493667125701904f
#define TWOPI_A  6.28318548202514648438f
#define TWOPI_B  (-1.74845552749343265e-7f)
#define MAGIC    12582912.0f    /* 1.5 * 2^23 */
#define ROWK     (-1.5339807878856412e-3f)   /* fl(-2*pi/4096) */

__global__ __launch_bounds__(NTHREADS, 1)
void fudft_hmma(const float* __restrict__ x,
                const float* __restrict__ t,
                const float* __restrict__ freqs,
                float* __restrict__ out) {
    // cols_sm doubles as the K-half exchange buffer in the epilogue (16 KB)
    __shared__ __align__(16) float cols_sm[NN];
    // X^T chunk, double-buffered: [c][kpair] f16x2, row stride XST u32
    __shared__ __align__(16) uint32_t xsh[2 * XBUF];   // 17.4 KB

    const int tid  = threadIdx.x;
    const int wid  = tid >> 5;
    const int lane = tid & 31;
    const int wg   = wid & 7;       // row group 0..7 (16 rows each)
    const int kh   = wid >> 3;      // K-half 0/1
    const int g    = lane >> 2;     // 0..7
    const int qid  = lane & 3;      // 0..3

    const int bx    = blockIdx.x;   // 0..127
    const int stile = bx & (STILES - 1);
    const int b     = bx >> 5;

    // ---- stage cols for the whole batch row (once) ----
    {
        const float4* t4 = (const float4*)(t + (size_t)b * NN);
        float4* c4 = (float4*)cols_sm;
#pragma unroll
        for (int r = 0; r < NN / 4 / NTHREADS; ++r) {
            float4 v = t4[tid + NTHREADS * r];
            v.x *= 4095.0f; v.y *= 4095.0f; v.z *= 4095.0f; v.w *= 4095.0f;
            c4[tid + NTHREADS * r] = v;
        }
    }

    // ---- per-thread row frequencies (A-fragment rows g and g+8) ----
    const int s_base = stile * 128 + wg * 16;
    const float rs0 = (freqs[s_base + g]     * 4095.0f) * ROWK;
    const float rs1 = (freqs[s_base + g + 8] * 4095.0f) * ROWK;
    const ull rs0_2 = pk2(rs0, rs0);
    const ull rs1_2 = pk2(rs1, rs1);
    const ull inv2pi2 = pk2(INV2PI, INV2PI);
    const ull magic2  = pk2(MAGIC, MAGIC);
    const ull nmagic2 = pk2(-MAGIC, -MAGIC);
    const ull nA2     = pk2(-TWOPI_A, -TWOPI_A);
    const ull nB2     = pk2(-TWOPI_B, -TWOPI_B);

    float dre[4][4], dim[4][4];
#pragma unroll
    for (int nt = 0; nt < 4; ++nt)
#pragma unroll
        for (int j = 0; j < 4; ++j) { dre[nt][j] = 0.0f; dim[nt][j] = 0.0f; }

    // ---- ldmatrix per-lane row addressing ----
    // x4 covers matrices m = (nt,h): m0=(0,0) m1=(0,1) m2=(1,0) m3=(1,1);
    // lane t: matrix t>>3, row t&7. Second ldsm4 covers nt+2 (c += 16).
    const uint32_t xsh_base = (uint32_t)__cvta_generic_to_shared(xsh);
    const int lm_m  = lane >> 3;
    const int lm_c  = 8 * (lm_m >> 1) + (lane & 7);
    const uint32_t lm_i0 = (uint32_t)(lm_c * XST + 4 * (lm_m & 1) + kh * 32);

    // ---- staging decomposition ----
    const float4* xg = (const float4*)(x + (size_t)b * NN * CC);
    const int kk   = tid >> 3;        // 0..63 (k row of v0; v1 is k+64)
    const int aa   = tid & 7;         // c block: c0 = 4*aa
    const int kodd = kk & 1;
    const int kp   = kk >> 1;         // k-pair col (v0); v1: +32
    const int c0   = aa * 4;

    // prefetch chunk 0
    float4 v0 = xg[tid];
    float4 v1 = xg[tid + NTHREADS];

    // stage chunk 0 into buffer 0
    {
        uint32_t* dst = xsh;
#pragma unroll
        for (int h = 0; h < 2; ++h) {
            const float4 v = h ? v1 : v0;
            const int col = kp + 32 * h;
            uint32_t q0 = f2h2(v.x, v.y);
            uint32_t q1 = f2h2(v.z, v.w);
            uint32_t s0 = __shfl_xor_sync(0xffffffffu, q0, 8);
            uint32_t s1 = __shfl_xor_sync(0xffffffffu, q1, 8);
            if (!kodd) {
                dst[c0 * XST + col]       = __byte_perm(q0, s0, 0x5410);
                dst[(c0 + 1) * XST + col] = __byte_perm(q0, s0, 0x7632);
            } else {
                dst[(c0 + 2) * XST + col] = __byte_perm(s1, q1, 0x5410);
                dst[(c0 + 3) * XST + col] = __byte_perm(s1, q1, 0x7632);
            }
        }
    }
    __syncthreads();

#pragma unroll 1
    for (int st = 0; st < NSTAGE; ++st) {
        const int p = st & 1;

        // prefetch next chunk early (regs held through compute)
        if (st < NSTAGE - 1) {
            v0 = xg[(st + 1) * 1024 + tid];
            v1 = xg[(st + 1) * 1024 + tid + NTHREADS];
        }

        const float* cols_loc = cols_sm + st * KCH;
        uint32_t aA = xsh_base + (uint32_t)((p ? XBUF : 0) + lm_i0) * 4u;
        uint32_t aB = aA + 16 * XST * 4;

        // this warp covers k16-steps kh*64 .. kh*64+63 within the 128-k chunk
#pragma unroll
        for (int ks2 = 0; ks2 < 4; ++ks2) {
            const int k0 = kh * 64 + ks2 * 16;
            const ull cA = *(const ull*)(cols_loc + k0 + 2 * qid);
            const ull cB = *(const ull*)(cols_loc + k0 + 2 * qid + 8);

            ull p00 = mul2(rs0_2, cA), p01 = mul2(rs0_2, cB);
            ull p10 = mul2(rs1_2, cA), p11 = mul2(rs1_2, cB);
            ull m00 = fma2n(p00, inv2pi2, magic2), m01 = fma2n(p01, inv2pi2, magic2);
            ull m10 = fma2n(p10, inv2pi2, magic2), m11 = fma2n(p11, inv2pi2, magic2);
            ull k00 = add2(m00, nmagic2), k01 = add2(m01, nmagic2);
            ull k10 = add2(m10, nmagic2), k11 = add2(m11, nmagic2);
            ull r00 = fma2n(k00, nA2, p00); r00 = fma2n(k00, nB2, r00);
            ull r01 = fma2n(k01, nA2, p01); r01 = fma2n(k01, nB2, r01);
            ull r10 = fma2n(k10, nA2, p10); r10 = fma2n(k10, nB2, r10);
            ull r11 = fma2n(k11, nA2, p11); r11 = fma2n(k11, nB2, r11);
            const float2 f00 = upk2(r00), f01 = upk2(r01);
            const float2 f10 = upk2(r10), f11 = upk2(r11);

            uint32_t ac[4], as_[4];
            ac[0]  = f2h2(__cosf(f00.x), __cosf(f00.y));
            as_[0] = f2h2(__sinf(f00.x), __sinf(f00.y));
            ac[1]  = f2h2(__cosf(f10.x), __cosf(f10.y));
            as_[1] = f2h2(__sinf(f10.x), __sinf(f10.y));
            ac[2]  = f2h2(__cosf(f01.x), __cosf(f01.y));
            as_[2] = f2h2(__sinf(f01.x), __sinf(f01.y));
            ac[3]  = f2h2(__cosf(f11.x), __cosf(f11.y));
            as_[3] = f2h2(__sinf(f11.x), __sinf(f11.y));

            // B fragments: 2 x ldmatrix.x4 = b0,b1 for nt=0..3
            uint32_t bq[8];
            ldsm4(bq[0], bq[1], bq[2], bq[3], aA);
            ldsm4(bq[4], bq[5], bq[6], bq[7], aB);
            aA += 32; aB += 32;     // +8 u32 = next k16 step

#pragma unroll
            for (int nt = 0; nt < 4; ++nt) {
                mma16(dre[nt], ac,  bq[2 * nt], bq[2 * nt + 1]);
                mma16(dim[nt], as_, bq[2 * nt], bq[2 * nt + 1]);
            }
        }

        // stage next chunk into the other buffer (overlaps other warps' compute)
        if (st < NSTAGE - 1) {
            uint32_t* dst = xsh + (p ? 0 : XBUF);
#pragma unroll
            for (int h = 0; h < 2; ++h) {
                const float4 v = h ? v1 : v0;
                const int col = kp + 32 * h;
                uint32_t q0 = f2h2(v.x, v.y);
                uint32_t q1 = f2h2(v.z, v.w);
                uint32_t s0 = __shfl_xor_sync(0xffffffffu, q0, 8);
                uint32_t s1 = __shfl_xor_sync(0xffffffffu, q1, 8);
                if (!kodd) {
                    dst[c0 * XST + col]       = __byte_perm(q0, s0, 0x5410);
                    dst[(c0 + 1) * XST + col] = __byte_perm(q0, s0, 0x7632);
                } else {
                    dst[(c0 + 2) * XST + col] = __byte_perm(s1, q1, 0x5410);
                    dst[(c0 + 3) * XST + col] = __byte_perm(s1, q1, 0x7632);
                }
            }
        }
        __syncthreads();
    }

    // ---- merge K-halves through cols_sm in 2 phases (nt pair per phase) ----
    const int s0g = s_base + g;
    const int s1g = s0g + 8;
    const bool z0 = (s0g == 0) || (s0g == SS - 1);
    const bool z1 = (s1g == 0) || (s1g == SS - 1);
    float* o0 = out + ((size_t)b * SS + s0g) * CC;
    float* o1 = out + ((size_t)b * SS + s1g) * CC;

#pragma unroll
    for (int p = 0; p < 2; ++p) {
        if (kh == 1) {
            float4* ex = (float4*)cols_sm;
#pragma unroll
            for (int j = 0; j < 2; ++j) {
                const int nt = 2 * p + j;
                ex[(wg * 4 + j * 2)     * 32 + lane] = *(const float4*)dre[nt];
                ex[(wg * 4 + j * 2 + 1) * 32 + lane] = *(const float4*)dim[nt];
            }
        }
        __syncthreads();
        if (kh == 0) {
            const float4* ex = (const float4*)cols_sm;
#pragma unroll
            for (int j = 0; j < 2; ++j) {
                const int nt = 2 * p + j;
                float4 hre = ex[(wg * 4 + j * 2)     * 32 + lane];
                float4 him = ex[(wg * 4 + j * 2 + 1) * 32 + lane];
                float re0 = dre[nt][0] + hre.x, im0 = dim[nt][0] + him.x;
                float re1 = dre[nt][1] + hre.y, im1 = dim[nt][1] + him.y;
                float re2 = dre[nt][2] + hre.z, im2 = dim[nt][2] + him.z;
                float re3 = dre[nt][3] + hre.w, im3 = dim[nt][3] + him.w;
                const int c = nt * 8 + 2 * qid;
                float2 w;
                w.x = z0 ? 0.0f : sqrtf(fmaf(re0, re0, im0 * im0)) * 0.015625f;
                w.y = z0 ? 0.0f : sqrtf(fmaf(re1, re1, im1 * im1)) * 0.015625f;
                *(float2*)(o0 + c) = w;
                w.x = z1 ? 0.0f : sqrtf(fmaf(re2, re2, im2 * im2)) * 0.015625f;
                w.y = z1 ? 0.0f : sqrtf(fmaf(re3, re3, im3 * im3)) * 0.015625f;
                *(float2*)(o1 + c) = w;
            }
        }
        if (p == 0) __syncthreads();
    }
}

extern "C" void kernel_launch(void* const* d_in, const int* in_sizes, int n_in,
                              void* d_out, int out_size) {
    const float* x     = (const float*)d_in[0];   // [4,4096,32]
    const float* t     = (const float*)d_in[1];   // [4,4096]
    const float* freqs = (const float*)d_in[2];   // [4096]
    float* out = (float*)d_out;                   // [4,4096,32]

    fudft_hmma<<<BB * STILES, NTHREADS>>>(x, t, freqs, out);
}